// round 1
// baseline (speedup 1.0000x reference)
#include <cuda_runtime.h>
#include <cstdint>

#define NND 50000
#define NE  800000
#define HD  128          // H*D
#define NH  4
#define INDIM 256

// ---------------- scratch (no allocations allowed) ----------------
__device__ float    g_el[(size_t)NND * HD];      // 25.6 MB
__device__ float    g_er[(size_t)NND * HD];      // 25.6 MB
__device__ float    g_scores[(size_t)NE * NH];   // 12.8 MB (scores, then exp)
__device__ unsigned g_m[(size_t)NND * NH];       // encoded segment max
__device__ float    g_denom[(size_t)NND * NH];

// order-preserving float<->uint encode for atomicMax
__device__ __forceinline__ unsigned enc_f(float f) {
    unsigned u = __float_as_uint(f);
    return (u & 0x80000000u) ? ~u : (u | 0x80000000u);
}
__device__ __forceinline__ float dec_f(unsigned u) {
    return __uint_as_float((u & 0x80000000u) ? (u & 0x7FFFFFFFu) : ~u);
}
__device__ __forceinline__ float lrelu(float x) {
    return x > 0.f ? x : 0.2f * x;
}

// ---------------- K1: fused GEMM  el|er = h @ [W_src|W_dst] + b ----------------
// Block: 256 threads = 256 output columns (0..127 -> el, 128..255 -> er),
// 32 rows per block. h-tile in smem, broadcast LDS.128, FMA-bound.
__global__ void __launch_bounds__(256) k_gemm(const float* __restrict__ h,
                                              const float* __restrict__ Ws,
                                              const float* __restrict__ bs,
                                              const float* __restrict__ Wd,
                                              const float* __restrict__ bd) {
    __shared__ float4 hs[32][INDIM / 4];   // 32 KB
    const int c    = threadIdx.x;
    const int row0 = blockIdx.x * 32;

    #pragma unroll 8
    for (int r = 0; r < 32; r++) {
        int row = row0 + r;
        float v = (row < NND) ? h[(size_t)row * INDIM + c] : 0.f;
        reinterpret_cast<float*>(&hs[r][0])[c] = v;
    }
    __syncthreads();

    const float* Wc;
    float bias;
    int cc;
    if (c < HD) { Wc = Ws; cc = c;      bias = bs[cc]; }
    else        { Wc = Wd; cc = c - HD; bias = bd[cc]; }

    float acc[32];
    #pragma unroll
    for (int r = 0; r < 32; r++) acc[r] = bias;

    #pragma unroll 2
    for (int k = 0; k < INDIM; k += 4) {
        float w0 = Wc[(size_t)(k + 0) * HD + cc];
        float w1 = Wc[(size_t)(k + 1) * HD + cc];
        float w2 = Wc[(size_t)(k + 2) * HD + cc];
        float w3 = Wc[(size_t)(k + 3) * HD + cc];
        #pragma unroll
        for (int r = 0; r < 32; r++) {
            float4 h4 = hs[r][k >> 2];   // broadcast: same addr for all lanes
            acc[r] = fmaf(h4.x, w0, fmaf(h4.y, w1, fmaf(h4.z, w2, fmaf(h4.w, w3, acc[r]))));
        }
    }

    float* outp = (c < HD) ? g_el : g_er;
    #pragma unroll
    for (int r = 0; r < 32; r++) {
        int row = row0 + r;
        if (row < NND) outp[(size_t)row * HD + cc] = acc[r];
    }
}

// ---------------- K2: init (out section, denom, encoded max) ----------------
__global__ void k_init(float* __restrict__ out) {
    int i = blockIdx.x * blockDim.x + threadIdx.x;
    if (i < NND * HD) out[i] = 0.f;
    if (i < NND * NH) { g_denom[i] = 0.f; g_m[i] = 0u; }
}

// ---------------- K3: edge scores + segment max (warp per edge) ----------------
__global__ void __launch_bounds__(256) k_scores(const int* __restrict__ src,
                                                const int* __restrict__ dst,
                                                const float* __restrict__ attn) {
    int e    = (blockIdx.x * 256 + threadIdx.x) >> 5;
    int lane = threadIdx.x & 31;
    if (e >= NE) return;
    int s = __ldg(&src[e]);
    int d = __ldg(&dst[e]);

    // lane covers head = lane>>3, dims (lane&7)*4 .. +3  (layout h*32+d)
    float4 a4 = reinterpret_cast<const float4*>(g_el + (size_t)s * HD)[lane];
    float4 b4 = reinterpret_cast<const float4*>(g_er + (size_t)d * HD)[lane];
    float4 w4 = reinterpret_cast<const float4*>(attn)[lane];

    float sum = lrelu(a4.x + b4.x) * w4.x + lrelu(a4.y + b4.y) * w4.y +
                lrelu(a4.z + b4.z) * w4.z + lrelu(a4.w + b4.w) * w4.w;
    sum += __shfl_xor_sync(0xffffffffu, sum, 1);
    sum += __shfl_xor_sync(0xffffffffu, sum, 2);
    sum += __shfl_xor_sync(0xffffffffu, sum, 4);

    if ((lane & 7) == 0) {
        int hh = lane >> 3;
        g_scores[(size_t)e * NH + hh] = sum;
        atomicMax(&g_m[(size_t)d * NH + hh], enc_f(sum));
    }
}

// ---------------- K4: exp + segment sum (thread per edge*head) ----------------
__global__ void __launch_bounds__(256) k_expsum(const int* __restrict__ dst) {
    int i = blockIdx.x * 256 + threadIdx.x;
    if (i >= NE * NH) return;
    int e  = i >> 2;
    int hh = i & 3;
    int d  = __ldg(&dst[e]);
    float m  = dec_f(g_m[(size_t)d * NH + hh]);
    float ex = __expf(g_scores[i] - m);
    g_scores[i] = ex;
    atomicAdd(&g_denom[(size_t)d * NH + hh], ex);
}

// ---------------- K5: normalize + weighted scatter (warp per edge) ----------------
__global__ void __launch_bounds__(256) k_scatter(const int* __restrict__ src,
                                                 const int* __restrict__ dst,
                                                 float* __restrict__ out,
                                                 float* __restrict__ out_a,
                                                 int writeA) {
    int e    = (blockIdx.x * 256 + threadIdx.x) >> 5;
    int lane = threadIdx.x & 31;
    if (e >= NE) return;
    int s = __ldg(&src[e]);
    int d = __ldg(&dst[e]);

    int   hh  = lane >> 3;
    float ex  = g_scores[(size_t)e * NH + hh];
    float den = g_denom[(size_t)d * NH + hh];
    float av  = ex / den;

    if (writeA && lane < NH) {
        out_a[(size_t)e * NH + lane] =
            g_scores[(size_t)e * NH + lane] / g_denom[(size_t)d * NH + lane];
    }

    float4 m4 = reinterpret_cast<const float4*>(g_el + (size_t)s * HD)[lane];
    float* p  = out + (size_t)d * HD + lane * 4;
    asm volatile("red.global.add.v4.f32 [%0], {%1,%2,%3,%4};"
                 :: "l"(p), "f"(m4.x * av), "f"(m4.y * av), "f"(m4.z * av), "f"(m4.w * av)
                 : "memory");
}

// ---------------- launch ----------------
extern "C" void kernel_launch(void* const* d_in, const int* in_sizes, int n_in,
                              void* d_out, int out_size) {
    const float* h     = (const float*)d_in[0];
    const int*   src   = (const int*)  d_in[1];
    const int*   dst   = (const int*)  d_in[2];
    const float* W_src = (const float*)d_in[3];
    const float* b_src = (const float*)d_in[4];
    const float* W_dst = (const float*)d_in[5];
    const float* b_dst = (const float*)d_in[6];
    const float* attn  = (const float*)d_in[7];

    float* out   = (float*)d_out;
    float* out_a = out + (size_t)NND * HD;
    int writeA   = (out_size >= NND * HD + NE * NH) ? 1 : 0;

    k_gemm<<<(NND + 31) / 32, 256>>>(h, W_src, b_src, W_dst, b_dst);
    k_init<<<(NND * HD + 255) / 256, 256>>>(out);
    k_scores<<<(NE * 32 + 255) / 256, 256>>>(src, dst, attn);
    k_expsum<<<(NE * NH + 255) / 256, 256>>>(dst);
    k_scatter<<<(NE * 32 + 255) / 256, 256>>>(src, dst, out, out_a, writeA);
}

// round 2
// speedup vs baseline: 1.1156x; 1.1156x over previous
#include <cuda_runtime.h>
#include <cstdint>

#define NND 50000
#define NE  800000
#define HD  128          // H*D
#define NH  4
#define INDIM 256

// ---------------- scratch (no allocations allowed) ----------------
__device__ float g_el[(size_t)NND * HD];       // 25.6 MB
__device__ float g_er[(size_t)NND * HD];       // 25.6 MB
__device__ float g_scores[(size_t)NE * NH];    // raw edge scores, 12.8 MB
__device__ int   g_cnt[NND];
__device__ int   g_off[NND + 1];
__device__ int   g_cursor[NND];
__device__ int2  g_pairs[NE];                  // (edge id, src node)

__device__ __forceinline__ float lrelu(float x) {
    return x > 0.f ? x : 0.2f * x;
}

// ---------------- K1: fused GEMM  el|er = h @ [W_src|W_dst] + b ----------------
__global__ void __launch_bounds__(256) k_gemm(const float* __restrict__ h,
                                              const float* __restrict__ Ws,
                                              const float* __restrict__ bs,
                                              const float* __restrict__ Wd,
                                              const float* __restrict__ bd) {
    __shared__ float4 hs[32][INDIM / 4];   // 32 KB
    const int c    = threadIdx.x;
    const int row0 = blockIdx.x * 32;

    #pragma unroll 8
    for (int r = 0; r < 32; r++) {
        int row = row0 + r;
        float v = (row < NND) ? h[(size_t)row * INDIM + c] : 0.f;
        reinterpret_cast<float*>(&hs[r][0])[c] = v;
    }
    __syncthreads();

    const float* Wc;
    float bias;
    int cc;
    if (c < HD) { Wc = Ws; cc = c;      bias = bs[cc]; }
    else        { Wc = Wd; cc = c - HD; bias = bd[cc]; }

    float acc[32];
    #pragma unroll
    for (int r = 0; r < 32; r++) acc[r] = bias;

    #pragma unroll 2
    for (int k = 0; k < INDIM; k += 4) {
        float w0 = Wc[(size_t)(k + 0) * HD + cc];
        float w1 = Wc[(size_t)(k + 1) * HD + cc];
        float w2 = Wc[(size_t)(k + 2) * HD + cc];
        float w3 = Wc[(size_t)(k + 3) * HD + cc];
        #pragma unroll
        for (int r = 0; r < 32; r++) {
            float4 h4 = hs[r][k >> 2];
            acc[r] = fmaf(h4.x, w0, fmaf(h4.y, w1, fmaf(h4.z, w2, fmaf(h4.w, w3, acc[r]))));
        }
    }

    float* outp = (c < HD) ? g_el : g_er;
    #pragma unroll
    for (int r = 0; r < 32; r++) {
        int row = row0 + r;
        if (row < NND) outp[(size_t)row * HD + cc] = acc[r];
    }
}

// ---------------- CSR build ----------------
__global__ void k_zero() {
    int i = blockIdx.x * blockDim.x + threadIdx.x;
    if (i < NND) g_cnt[i] = 0;
}

__global__ void k_hist(const int* __restrict__ dst) {
    int e = blockIdx.x * blockDim.x + threadIdx.x;
    if (e < NE) atomicAdd(&g_cnt[dst[e]], 1);
}

// single-block exclusive scan of g_cnt -> g_off (+ copy to g_cursor)
__global__ void __launch_bounds__(1024) k_scan() {
    __shared__ int s[1024];
    const int tid = threadIdx.x;
    const int CH  = (NND + 1023) / 1024;   // 49
    const int base = tid * CH;

    int tsum = 0;
    for (int i = 0; i < CH; i++) {
        int idx = base + i;
        if (idx < NND) tsum += g_cnt[idx];
    }
    s[tid] = tsum;
    __syncthreads();
    for (int o = 1; o < 1024; o <<= 1) {
        int v = (tid >= o) ? s[tid - o] : 0;
        __syncthreads();
        s[tid] += v;
        __syncthreads();
    }
    int pref = s[tid] - tsum;   // exclusive prefix of this thread's chunk
    for (int i = 0; i < CH; i++) {
        int idx = base + i;
        if (idx < NND) {
            g_off[idx]    = pref;
            g_cursor[idx] = pref;
            pref += g_cnt[idx];
        }
    }
    if (tid == 1023) g_off[NND] = s[1023];
}

__global__ void k_bucket(const int* __restrict__ src, const int* __restrict__ dst) {
    int e = blockIdx.x * blockDim.x + threadIdx.x;
    if (e >= NE) return;
    int d = dst[e];
    int p = atomicAdd(&g_cursor[d], 1);
    g_pairs[p] = make_int2(e, src[e]);
}

// ---------------- K_dst: warp-per-dst online softmax + aggregate ----------------
__global__ void __launch_bounds__(256) k_dst(const float* __restrict__ attn,
                                             float* __restrict__ out,
                                             float* __restrict__ out_a,
                                             int writeA) {
    const int d    = (blockIdx.x * 256 + threadIdx.x) >> 5;
    const int lane = threadIdx.x & 31;
    if (d >= NND) return;

    const int start = g_off[d];
    const int cnt   = g_off[d + 1] - start;

    // lane covers head = lane>>3, dims (lane&7)*4..+3
    const float4 er4 = reinterpret_cast<const float4*>(g_er + (size_t)d * HD)[lane];
    const float4 w4  = reinterpret_cast<const float4*>(attn)[lane];

    float m = -1e30f, denom = 0.f;
    float4 acc = make_float4(0.f, 0.f, 0.f, 0.f);

    for (int i = 0; i < cnt; i++) {
        int2   p  = g_pairs[start + i];
        float4 a4 = reinterpret_cast<const float4*>(g_el + (size_t)p.y * HD)[lane];

        float sc = lrelu(a4.x + er4.x) * w4.x + lrelu(a4.y + er4.y) * w4.y +
                   lrelu(a4.z + er4.z) * w4.z + lrelu(a4.w + er4.w) * w4.w;
        sc += __shfl_xor_sync(0xffffffffu, sc, 1);
        sc += __shfl_xor_sync(0xffffffffu, sc, 2);
        sc += __shfl_xor_sync(0xffffffffu, sc, 4);   // per-head score, all 8 lanes of group

        if ((lane & 7) == 0)
            g_scores[(size_t)p.x * NH + (lane >> 3)] = sc;

        float mn    = fmaxf(m, sc);
        float scale = __expf(m - mn);
        float ex    = __expf(sc - mn);
        denom = denom * scale + ex;
        acc.x = fmaf(acc.x, scale, ex * a4.x);
        acc.y = fmaf(acc.y, scale, ex * a4.y);
        acc.z = fmaf(acc.z, scale, ex * a4.z);
        acc.w = fmaf(acc.w, scale, ex * a4.w);
        m = mn;
    }

    float rden = (cnt > 0) ? 1.f / denom : 0.f;

    float4 o4 = make_float4(acc.x * rden, acc.y * rden, acc.z * rden, acc.w * rden);
    reinterpret_cast<float4*>(out + (size_t)d * HD)[lane] = o4;

    if (!writeA || cnt == 0) return;

    __threadfence_block();
    __syncwarp();

    // pass 2: attention weights. lane handles edge slot j+(lane>>2), head lane&3
    int src_lane = (lane & 3) << 3;
    float mh  = __shfl_sync(0xffffffffu, m,    src_lane);
    float rdh = __shfl_sync(0xffffffffu, rden, src_lane);
    for (int j = 0; j < cnt; j += 8) {
        int i = j + (lane >> 2);
        if (i < cnt) {
            int   eid = g_pairs[start + i].x;
            float sc  = g_scores[(size_t)eid * NH + (lane & 3)];
            out_a[(size_t)eid * NH + (lane & 3)] = __expf(sc - mh) * rdh;
        }
    }
}

// ---------------- launch ----------------
extern "C" void kernel_launch(void* const* d_in, const int* in_sizes, int n_in,
                              void* d_out, int out_size) {
    const float* h     = (const float*)d_in[0];
    const int*   src   = (const int*)  d_in[1];
    const int*   dst   = (const int*)  d_in[2];
    const float* W_src = (const float*)d_in[3];
    const float* b_src = (const float*)d_in[4];
    const float* W_dst = (const float*)d_in[5];
    const float* b_dst = (const float*)d_in[6];
    const float* attn  = (const float*)d_in[7];

    float* out   = (float*)d_out;
    float* out_a = out + (size_t)NND * HD;
    int writeA   = (out_size >= NND * HD + NE * NH) ? 1 : 0;

    k_zero  <<<(NND + 255) / 256, 256>>>();
    k_hist  <<<(NE + 255) / 256, 256>>>(dst);
    k_scan  <<<1, 1024>>>();
    k_bucket<<<(NE + 255) / 256, 256>>>(src, dst);
    k_gemm  <<<(NND + 31) / 32, 256>>>(h, W_src, b_src, W_dst, b_dst);
    k_dst   <<<(NND * 32 + 255) / 256, 256>>>(attn, out, out_a, writeA);
}